// round 15
// baseline (speedup 1.0000x reference)
#include <cuda_runtime.h>
#include <stdint.h>

// Banded outer product: out[b,i,j] = s[b,i]*e[b,j] for 0 <= j-i <= 15, else 0.
// B=16, L=4096. Output 1.073 GB fp32 -> store-bound at the path-independent
// LTS cap (~7.0 TB/s measured for every store flavor / block shape).
//
// R15: minimum-traffic kernel = single-pass predicated stores (R1 value path,
// best kernel time 144.7us, no duplicate band writes) x half-row blocks
// (R8/R9 best shape). Every output chunk is stored exactly once.
// 131072 blocks x 256 threads x 2 float4.

#define LDIM 4096
#define BAND 15

__global__ __launch_bounds__(256, 8)
void band_outer_kernel(const float* __restrict__ s,
                       const float* __restrict__ e,
                       float* __restrict__ out)
{
    const unsigned blk = blockIdx.x;
    const int row  = blk >> 1;               // b*L + i
    const int half = blk & 1;                // 0: chunks [0,511], 1: [512,1023]
    const int i    = row & (LDIM - 1);
    const int t    = threadIdx.x;

    const float sv = __ldg(&s[row]);
    const float* __restrict__ erow = e + (row & ~(LDIM - 1));

    float4* __restrict__ orow =
        reinterpret_cast<float4*>(out) + (size_t)row * (LDIM / 4);

    const int cbase = half << 9;              // 0 or 512
    const int lo4 = i >> 2;                   // first float4 chunk in band
    const int hi4 = (i + BAND) >> 2;          // last  float4 chunk in band

#pragma unroll
    for (int k = 0; k < 2; ++k) {
        const int c4 = cbase + t + k * 256;   // float4 index within the row
        float4 v = make_float4(0.f, 0.f, 0.f, 0.f);

        if (c4 >= lo4 && c4 <= hi4) {         // <=5 of 1024 chunks per row
            const int j = c4 << 2;
            if ((unsigned)(j     - i) <= BAND) v.x = sv * __ldg(&erow[j]);
            if ((unsigned)(j + 1 - i) <= BAND) v.y = sv * __ldg(&erow[j + 1]);
            if ((unsigned)(j + 2 - i) <= BAND) v.z = sv * __ldg(&erow[j + 2]);
            if ((unsigned)(j + 3 - i) <= BAND) v.w = sv * __ldg(&erow[j + 3]);
        }
        // exactly one streaming store per chunk — minimum possible traffic
        __stcs(&orow[c4], v);
    }
}

extern "C" void kernel_launch(void* const* d_in, const int* in_sizes, int n_in,
                              void* d_out, int out_size)
{
    const float* s = (const float*)d_in[0];
    const float* e = (const float*)d_in[1];
    float* out = (float*)d_out;

    // 2 blocks per row, 16*4096 rows
    band_outer_kernel<<<2 * 16 * LDIM, 256>>>(s, e, out);
}

// round 16
// speedup vs baseline: 1.0015x; 1.0015x over previous
#include <cuda_runtime.h>
#include <stdint.h>

// Banded outer product: out[b,i,j] = s[b,i]*e[b,j] for 0 <= j-i <= 15, else 0.
// B=16, L=4096. Output 1.073 GB fp32 -> pure store-bound.
//
// FINAL. Session conclusion: every store flavor (stcs/stcg/stwt), every block
// shape >= 65536 blocks, and both value-path schemes (zero-fill+overwrite vs
// single-pass predicated) pin at 6965-7028 GB/s — the path-independent
// LTS/HBM-write structural ceiling. This config (R9) holds the best measured
// wall time: 146.4us, rel_err 0.
//
// 131072 half-row blocks x 256 threads x 2 float4 (8 KB/block).
// Phase 1: unconditional zero fill (dependency-free store stream).
// Phase 2: owning threads overwrite the <=5 band chunks per row
// (same thread + same address -> program order gives the band value last).

#define LDIM 4096
#define BAND 15

__global__ __launch_bounds__(256, 8)
void band_outer_kernel(const float* __restrict__ s,
                       const float* __restrict__ e,
                       float* __restrict__ out)
{
    const unsigned blk = blockIdx.x;
    const int row  = blk >> 1;               // b*L + i
    const int half = blk & 1;                // 0: chunks [0,511], 1: [512,1023]
    const int i    = row & (LDIM - 1);
    const int t    = threadIdx.x;

    const float sv = __ldg(&s[row]);
    const float* __restrict__ erow = e + (row & ~(LDIM - 1));

    float4* __restrict__ orow =
        reinterpret_cast<float4*>(out) + (size_t)row * (LDIM / 4);

    const int cbase = half << 9;              // 0 or 512

    // ---- phase 1: unconditional zero fill (2 independent STG.128/thread) ----
    const float4 z = make_float4(0.f, 0.f, 0.f, 0.f);
    __stcs(&orow[cbase + t],       z);
    __stcs(&orow[cbase + t + 256], z);

    // ---- phase 2: overwrite band chunks if they land in this half ----
    const int lo4 = i >> 2;
    const int hi4 = (i + BAND) >> 2;          // <= 1023 always

#pragma unroll
    for (int k = 0; k < 2; ++k) {
        const int c4 = cbase + t + k * 256;
        if (c4 >= lo4 && c4 <= hi4) {
            const int j = c4 << 2;
            float4 v;
            v.x = ((unsigned)(j     - i) <= BAND) ? sv * __ldg(&erow[j])     : 0.f;
            v.y = ((unsigned)(j + 1 - i) <= BAND) ? sv * __ldg(&erow[j + 1]) : 0.f;
            v.z = ((unsigned)(j + 2 - i) <= BAND) ? sv * __ldg(&erow[j + 2]) : 0.f;
            v.w = ((unsigned)(j + 3 - i) <= BAND) ? sv * __ldg(&erow[j + 3]) : 0.f;
            __stcs(&orow[c4], v);   // same thread as the zero store -> ordered
        }
    }
}

extern "C" void kernel_launch(void* const* d_in, const int* in_sizes, int n_in,
                              void* d_out, int out_size)
{
    const float* s = (const float*)d_in[0];
    const float* e = (const float*)d_in[1];
    float* out = (float*)d_out;

    // 2 blocks per row, 16*4096 rows
    band_outer_kernel<<<2 * 16 * LDIM, 256>>>(s, e, out);
}

// round 17
// speedup vs baseline: 1.0063x; 1.0048x over previous
#include <cuda_runtime.h>
#include <stdint.h>

// Banded outer product: out[b,i,j] = s[b,i]*e[b,j] for 0 <= j-i <= 15, else 0.
// B=16, L=4096. Output 1.073 GB fp32 -> store-bound at the path-independent
// LTS/HBM-write ceiling (~7.0 TB/s measured across all prior variants).
//
// R17: last untested granularity step — smaller CTAs, not just more blocks.
// Quarter-row per block: 262144 blocks x 128 threads x 2 float4 (4 KB/block),
// occ 16 CTAs/SM (same 2048 thr/SM as 256x8, but 2x independent CTA streams).
// Zero-fill first, then owning threads overwrite the <=5 band chunks
// (same thread + same address -> program order gives the band value last).

#define LDIM 4096
#define BAND 15

__global__ __launch_bounds__(128, 16)
void band_outer_kernel(const float* __restrict__ s,
                       const float* __restrict__ e,
                       float* __restrict__ out)
{
    const unsigned blk = blockIdx.x;
    const int row  = blk >> 2;               // b*L + i
    const int q    = blk & 3;                // quarter: chunks [q*256, q*256+255]
    const int i    = row & (LDIM - 1);
    const int t    = threadIdx.x;

    const float sv = __ldg(&s[row]);
    const float* __restrict__ erow = e + (row & ~(LDIM - 1));

    float4* __restrict__ orow =
        reinterpret_cast<float4*>(out) + (size_t)row * (LDIM / 4);

    const int cbase = q << 8;                 // 0, 256, 512, 768

    // ---- phase 1: unconditional zero fill (2 independent STG.128/thread) ----
    const float4 z = make_float4(0.f, 0.f, 0.f, 0.f);
    __stcs(&orow[cbase + t],       z);
    __stcs(&orow[cbase + t + 128], z);

    // ---- phase 2: overwrite band chunks if they land in this quarter ----
    const int lo4 = i >> 2;
    const int hi4 = (i + BAND) >> 2;          // <= 1023 always

#pragma unroll
    for (int k = 0; k < 2; ++k) {
        const int c4 = cbase + t + k * 128;
        if (c4 >= lo4 && c4 <= hi4) {
            const int j = c4 << 2;
            float4 v;
            v.x = ((unsigned)(j     - i) <= BAND) ? sv * __ldg(&erow[j])     : 0.f;
            v.y = ((unsigned)(j + 1 - i) <= BAND) ? sv * __ldg(&erow[j + 1]) : 0.f;
            v.z = ((unsigned)(j + 2 - i) <= BAND) ? sv * __ldg(&erow[j + 2]) : 0.f;
            v.w = ((unsigned)(j + 3 - i) <= BAND) ? sv * __ldg(&erow[j + 3]) : 0.f;
            __stcs(&orow[c4], v);   // same thread as the zero store -> ordered
        }
    }
}

extern "C" void kernel_launch(void* const* d_in, const int* in_sizes, int n_in,
                              void* d_out, int out_size)
{
    const float* s = (const float*)d_in[0];
    const float* e = (const float*)d_in[1];
    float* out = (float*)d_out;

    // 4 blocks per row, 16*4096 rows
    band_outer_kernel<<<4 * 16 * LDIM, 128>>>(s, e, out);
}